// round 12
// baseline (speedup 1.0000x reference)
#include <cuda_runtime.h>
#include <cuda_fp16.h>
#include <math.h>
#include <stdint.h>

#define C_IN   384
#define C_MID  1536
#define EMB_D  1024
#define BATCH  16
#define HW     1024
#define GROUPS 32
#define CPG    12
#define EPSV   1e-5f

#define BM 128
#define LDT 132

typedef unsigned int u32;

// ---------------- device scratch ----------------
__device__ u32 g_h[(size_t)BATCH * (C_MID / 2) * HW];   // h fp16 pair-major
__device__ u32 g_xn[(size_t)BATCH * (C_IN / 2) * HW];   // xn fp16 pair-major
__device__ float g_embout[BATCH * 2 * C_MID];
__device__ __half g_w1f[C_MID * C_IN];
__device__ __half g_w2f[C_IN * C_MID];

// ---------------- helpers ----------------
__device__ __forceinline__ u32 packh(float lo, float hi) {
    __half2 h = __floats2half2_rn(lo, hi);
    return *(u32*)&h;
}
__device__ __forceinline__ void mma16(float* c, const u32* a, const u32* b) {
    asm volatile(
        "mma.sync.aligned.m16n8k16.row.col.f32.f16.f16.f32 "
        "{%0,%1,%2,%3}, {%4,%5,%6,%7}, {%8,%9}, {%0,%1,%2,%3};\n"
        : "+f"(c[0]), "+f"(c[1]), "+f"(c[2]), "+f"(c[3])
        : "r"(a[0]), "r"(a[1]), "r"(a[2]), "r"(a[3]), "r"(b[0]), "r"(b[1]));
}
__device__ __forceinline__ void cp16(const void* s, const void* g) {
    uint32_t sa = (uint32_t)__cvta_generic_to_shared(s);
    asm volatile("cp.async.cg.shared.global [%0], [%1], 16;\n" :: "r"(sa), "l"(g));
}
#define CPCOMMIT() asm volatile("cp.async.commit_group;\n" ::: "memory")
#define CPWAIT(n)  asm volatile("cp.async.wait_group %0;\n" :: "n"(n) : "memory")

// ---------------------------------------------------------------------------
// Fused prep: w1 frag-order, w2 frag-order, emb GEMM.
// wtrans layout per (mb, 32k-stage s): 2048 u32 = [kk(2)][mt(8)][lane(32)][q(4)]
// ---------------------------------------------------------------------------
__device__ __forceinline__ void wtrans_one(const float* __restrict__ w,
                                           __half* __restrict__ wf,
                                           int i, int K) {
    int m = i / K, k = i % K;
    int S = K >> 5;
    int mb = m >> 7, s = k >> 5;
    int kk = (k >> 4) & 1;
    int mt = (m >> 4) & 7;
    int r = m & 15, c = k & 15;
    int q = (r >> 3) | ((c >> 3) << 1);
    int lane = (r & 7) * 4 + ((c & 7) >> 1);
    size_t b32i = ((((size_t)(mb * S + s) * 2 + kk) * 8 + mt) * 32 + lane) * 4 + q;
    wf[b32i * 2 + (c & 1)] = __float2half_rn(w[i]);
}

#define WBLK ((C_MID * C_IN) / 256)

__global__ void __launch_bounds__(256) prep(const float* __restrict__ w1,
                                            const float* __restrict__ w2,
                                            const float* __restrict__ emb,
                                            const float* __restrict__ we,
                                            const float* __restrict__ be) {
    int bx = blockIdx.x;
    if (bx < WBLK) {
        wtrans_one(w1, g_w1f, bx * 256 + threadIdx.x, C_IN);
    } else if (bx < 2 * WBLK) {
        wtrans_one(w2, g_w2f, (bx - WBLK) * 256 + threadIdx.x, C_MID);
    } else {
        int w = threadIdx.x >> 5, lane = threadIdx.x & 31;
        int j = (bx - 2 * WBLK) * 8 + w;
        const float4* wrow = (const float4*)(we + (size_t)j * EMB_D);
        float4 wv[8];
#pragma unroll
        for (int i = 0; i < 8; i++) wv[i] = wrow[lane + 32 * i];
#pragma unroll
        for (int b = 0; b < BATCH; b++) {
            const float4* er = (const float4*)(emb + (size_t)b * EMB_D);
            float acc = 0.f;
#pragma unroll
            for (int i = 0; i < 8; i++) {
                float4 ev = __ldg(&er[lane + 32 * i]);
                acc += wv[i].x * ev.x + wv[i].y * ev.y + wv[i].z * ev.z + wv[i].w * ev.w;
            }
#pragma unroll
            for (int off = 16; off; off >>= 1) acc += __shfl_xor_sync(0xffffffffu, acc, off);
            if (lane == 0) g_embout[b * (2 * C_MID) + j] = acc + be[j];
        }
    }
}

// ---------------------------------------------------------------------------
__global__ void __launch_bounds__(256) gn_xn(const float* __restrict__ x,
                                             const float* __restrict__ gn_w,
                                             const float* __restrict__ gn_b) {
    int g = blockIdx.x, b = blockIdx.y;
    const float* xp = x + ((size_t)b * C_IN + (size_t)g * CPG) * HW;
    int t = threadIdx.x;
    const int N = CPG * HW;

    float s = 0.f, ss = 0.f;
    for (int i = t * 4; i < N; i += 256 * 4) {
        float4 v = *(const float4*)(xp + i);
        s  += v.x + v.y + v.z + v.w;
        ss += v.x * v.x + v.y * v.y + v.z * v.z + v.w * v.w;
    }
#pragma unroll
    for (int off = 16; off; off >>= 1) {
        s  += __shfl_xor_sync(0xffffffffu, s, off);
        ss += __shfl_xor_sync(0xffffffffu, ss, off);
    }
    __shared__ float rs[8], rss[8];
    if ((t & 31) == 0) { rs[t >> 5] = s; rss[t >> 5] = ss; }
    __syncthreads();
    __shared__ float smu, srst;
    if (t == 0) {
        float S = 0.f, SS = 0.f;
#pragma unroll
        for (int i = 0; i < 8; i++) { S += rs[i]; SS += rss[i]; }
        float mu  = S / (float)N;
        float var = SS / (float)N - mu * mu;
        smu = mu; srst = rsqrtf(var + EPSV);
    }
    __syncthreads();
    const float mu = smu, rst = srst;

    const int n4 = t * 4;
#pragma unroll
    for (int j = 0; j < CPG / 2; j++) {
        int c0 = g * CPG + j * 2;
        float a0 = rst * gn_w[c0],     b0 = gn_b[c0]     - mu * a0;
        float a1 = rst * gn_w[c0 + 1], b1 = gn_b[c0 + 1] - mu * a1;
        float4 x0 = *(const float4*)(x + ((size_t)b * C_IN + c0)     * HW + n4);
        float4 x1 = *(const float4*)(x + ((size_t)b * C_IN + c0 + 1) * HW + n4);
        uint4 o;
        o.x = packh(x0.x * a0 + b0, x1.x * a1 + b1);
        o.y = packh(x0.y * a0 + b0, x1.y * a1 + b1);
        o.z = packh(x0.z * a0 + b0, x1.z * a1 + b1);
        o.w = packh(x0.w * a0 + b0, x1.w * a1 + b1);
        *(uint4*)(g_xn + ((size_t)b * (C_IN / 2) + (c0 >> 1)) * HW + n4) = o;
    }
}

// ---------------------------------------------------------------------------
// fp16 m16n8k16 GEMM. Template: tile N (TBN), BK, NSTAGE, occupancy hint.
// TBN=128 -> 8 warps 2m x 4n (MI=4). TBN=64 -> 8 warps 4m x 2n (MI=2).
// EPI==1: silu+FiLM -> g_h fp16 pair-major. EPI==2: out = x + acc + b2.
// ---------------------------------------------------------------------------
template <int KTOT, int MTOT, int EPI, int BK, int NST, int TBN, int OCC>
__global__ void __launch_bounds__(256, OCC) mma_gemm(
    const __half* __restrict__ Wf,
    const u32* __restrict__ Bsrc,
    const float* __restrict__ bias,
    const float* __restrict__ xres,
    float* __restrict__ outp)
{
    constexpr int KK   = BK / 16;
    constexpr int MI   = (TBN == 128) ? 4 : 2;
    constexpr int LDB  = TBN + 8;
    constexpr int A_U  = BM * BK / 2;
    constexpr int B_U  = (BK / 2) * LDB;
    constexpr int STG  = A_U + B_U;
    constexpr int S    = KTOT / BK;
    constexpr int MAXW = NST - 2;
    constexpr int BGRP = TBN / 4;

    extern __shared__ float dsm[];
    u32* sm = (u32*)(((uintptr_t)dsm + 1023) & ~(uintptr_t)1023);

    const int t = threadIdx.x;
    const int b = blockIdx.z;
    const int m0 = blockIdx.x * BM;
    const int p0 = blockIdx.y * TBN;
    const int wid = t >> 5, lane = t & 31;
    const int gr = lane >> 2, tg = lane & 3;
    const int wm = (TBN == 128) ? (wid >> 2) : (wid >> 1);
    const int wn = (TBN == 128) ? (wid & 3) : (wid & 1);
    const int mtb = wm * MI;
    const int nw = wn * 32;

    const u32* Wb = (const u32*)Wf + (size_t)blockIdx.x * (KTOT / 32) * 2048;
    const u32* Bb = Bsrc + (size_t)b * (KTOT / 2) * HW + p0;

    float acc[MI][4][4];
#pragma unroll
    for (int i = 0; i < MI; i++)
#pragma unroll
        for (int j = 0; j < 4; j++)
#pragma unroll
            for (int q = 0; q < 4; q++) acc[i][j][q] = 0.f;

    auto fill = [&](int st) {
        u32* sA = sm + (st % NST) * STG;
        u32* sB = sA + A_U;
        const u32* gA = Wb + (size_t)st * A_U;
#pragma unroll
        for (int it = 0; it < A_U / 1024; it++)
            cp16(sA + it * 1024 + t * 4, gA + it * 1024 + t * 4);
#pragma unroll
        for (int it = 0; it < ((BK / 2) * BGRP) / 256; it++) {
            int idx = t + it * 256;
            int row = idx / BGRP, gq = (idx % BGRP) * 4;
            cp16(sB + row * LDB + gq, Bb + (size_t)(st * (BK / 2) + row) * HW + gq);
        }
        CPCOMMIT();
    };

#pragma unroll
    for (int p = 0; p < NST - 1; p++) fill(p);

    for (int s = 0; s < S; s++) {
        const int rem = S - 1 - s;
        if (MAXW >= 3 && rem >= 3)      { CPWAIT(3); }
        else if (MAXW >= 2 && rem >= 2) { CPWAIT(2); }
        else if (rem >= 1)              { CPWAIT(1); }
        else                            { CPWAIT(0); }
        __syncthreads();
        if (s + NST - 1 < S) fill(s + NST - 1);

        const u32* sA = sm + (s % NST) * STG;
        const u32* sB = sA + A_U;

#pragma unroll
        for (int kk = 0; kk < KK; kk++) {
            u32 af[MI][4];
#pragma unroll
            for (int mi = 0; mi < MI; mi++) {
                const uint4 v = *(const uint4*)(sA + ((kk * 8 + mtb + mi) * 32 + lane) * 4);
                af[mi][0] = v.x; af[mi][1] = v.y; af[mi][2] = v.z; af[mi][3] = v.w;
            }
            u32 bf[4][2];
#pragma unroll
            for (int ni = 0; ni < 4; ni++) {
                int nc = nw + ni * 8 + gr;
                bf[ni][0] = sB[(kk * 8 + tg)     * LDB + nc];
                bf[ni][1] = sB[(kk * 8 + tg + 4) * LDB + nc];
            }
#pragma unroll
            for (int mi = 0; mi < MI; mi++)
#pragma unroll
                for (int ni = 0; ni < 4; ni++)
                    mma16(acc[mi][ni], af[mi], bf[ni]);
        }
    }
    __syncthreads();

    // ---------------- epilogue ----------------
    if (EPI == 1) {
        float* tile = (float*)sm;
        const float* sc = g_embout + b * 2 * C_MID;
#pragma unroll
        for (int mi = 0; mi < MI; mi++) {
#pragma unroll
            for (int half = 0; half < 2; half++) {
                int rl = (mtb + mi) * 16 + gr + half * 8;
                int r = m0 + rl;
                float bi    = bias[r];
                float scale = 1.f + sc[r];
                float shift = sc[C_MID + r];
#pragma unroll
                for (int ni = 0; ni < 4; ni++) {
                    float v0 = acc[mi][ni][half * 2]     + bi;
                    float v1 = acc[mi][ni][half * 2 + 1] + bi;
                    v0 = v0 / (1.f + __expf(-v0));
                    v1 = v1 / (1.f + __expf(-v1));
                    float2 o = make_float2(v0 * scale + shift, v1 * scale + shift);
                    *(float2*)(tile + rl * LDT + nw + ni * 8 + tg * 2) = o;
                }
            }
        }
        __syncthreads();
#pragma unroll
        for (int it = 0; it < 8; it++) {
            int idx = t + it * 256;
            int p = idx >> 5, c4 = (idx & 31) * 4;
            const float* r0 = tile + (2 * p)     * LDT + c4;
            const float* r1 = tile + (2 * p + 1) * LDT + c4;
            uint4 o;
            o.x = packh(r0[0], r1[0]);
            o.y = packh(r0[1], r1[1]);
            o.z = packh(r0[2], r1[2]);
            o.w = packh(r0[3], r1[3]);
            *(uint4*)(g_h + ((size_t)b * (C_MID / 2) + (m0 >> 1) + p) * HW + p0 + c4) = o;
        }
    } else {
#pragma unroll
        for (int mi = 0; mi < MI; mi++) {
#pragma unroll
            for (int half = 0; half < 2; half++) {
                int r = m0 + (mtb + mi) * 16 + gr + half * 8;
                float bi = bias[r];
                const float* xrow = xres + ((size_t)b * C_IN + r) * HW + p0 + nw;
                float* orow = outp + ((size_t)b * C_IN + r) * HW + p0 + nw;
#pragma unroll
                for (int ni = 0; ni < 4; ni++) {
                    float2 xv = *(const float2*)(xrow + ni * 8 + tg * 2);
                    float2 o = make_float2(xv.x + acc[mi][ni][half * 2]     + bi,
                                           xv.y + acc[mi][ni][half * 2 + 1] + bi);
                    *(float2*)(orow + ni * 8 + tg * 2) = o;
                }
            }
        }
    }
}

// ---------------------------------------------------------------------------
extern "C" void kernel_launch(void* const* d_in, const int* in_sizes, int n_in,
                              void* d_out, int out_size) {
    const float* x    = (const float*)d_in[0];
    const float* emb  = (const float*)d_in[1];
    const float* gn_w = (const float*)d_in[2];
    const float* gn_b = (const float*)d_in[3];
    const float* w1   = (const float*)d_in[4];
    const float* b1   = (const float*)d_in[5];
    const float* we   = (const float*)d_in[6];
    const float* be   = (const float*)d_in[7];
    const float* w2   = (const float*)d_in[8];
    const float* b2   = (const float*)d_in[9];
    float* out = (float*)d_out;

    u32 *hbuf, *xnbuf;
    __half *w1f, *w2f;
    cudaGetSymbolAddress((void**)&hbuf, g_h);
    cudaGetSymbolAddress((void**)&xnbuf, g_xn);
    cudaGetSymbolAddress((void**)&w1f, g_w1f);
    cudaGetSymbolAddress((void**)&w2f, g_w2f);

    // GEMM1: 128x128, BK=64, NST=3, occ 2. stage = 4096 + 32*136 = 8448 u32
    constexpr int SMEMB1 = 3 * (4096 + 32 * 136) * 4 + 1024;
    // GEMM2: 128x64, BK=32, NST=4, occ 3. stage = 2048 + 16*72 = 3200 u32
    constexpr int SMEMB2 = 4 * (2048 + 16 * 72) * 4 + 1024;

    cudaFuncSetAttribute((const void*)mma_gemm<C_IN, C_MID, 1, 64, 3, 128, 2>,
                         cudaFuncAttributeMaxDynamicSharedMemorySize, SMEMB1);
    cudaFuncSetAttribute((const void*)mma_gemm<C_MID, C_IN, 2, 32, 4, 64, 3>,
                         cudaFuncAttributeMaxDynamicSharedMemorySize, SMEMB2);

    prep<<<2 * WBLK + (2 * C_MID) / 8, 256>>>(w1, w2, emb, we, be);
    gn_xn<<<dim3(GROUPS, BATCH), 256>>>(x, gn_w, gn_b);

    mma_gemm<C_IN, C_MID, 1, 64, 3, 128, 2><<<dim3(C_MID / BM, HW / 128, BATCH), 256, SMEMB1>>>(
        w1f, xnbuf, b1, nullptr, nullptr);
    mma_gemm<C_MID, C_IN, 2, 32, 4, 64, 3><<<dim3(C_IN / BM, HW / 64, BATCH), 256, SMEMB2>>>(
        w2f, hbuf, b2, x, out);
}

// round 13
// speedup vs baseline: 1.0601x; 1.0601x over previous
#include <cuda_runtime.h>
#include <cuda_fp16.h>
#include <math.h>
#include <stdint.h>

#define C_IN   384
#define C_MID  1536
#define EMB_D  1024
#define BATCH  16
#define HW     1024
#define GROUPS 32
#define CPG    12
#define EPSV   1e-5f

#define BM 128
#define LDT 132

typedef unsigned int u32;

// ---------------- device scratch ----------------
__device__ u32 g_h[(size_t)BATCH * (C_MID / 2) * HW];   // h fp16 pair-major
__device__ u32 g_xn[(size_t)BATCH * (C_IN / 2) * HW];   // xn fp16 pair-major
__device__ float g_embout[BATCH * 2 * C_MID];
__device__ __half g_w1f[C_MID * C_IN];
__device__ __half g_w2f[C_IN * C_MID];

// ---------------- helpers ----------------
__device__ __forceinline__ u32 packh(float lo, float hi) {
    __half2 h = __floats2half2_rn(lo, hi);
    return *(u32*)&h;
}
__device__ __forceinline__ void mma16(float* c, const u32* a, const u32* b) {
    asm volatile(
        "mma.sync.aligned.m16n8k16.row.col.f32.f16.f16.f32 "
        "{%0,%1,%2,%3}, {%4,%5,%6,%7}, {%8,%9}, {%0,%1,%2,%3};\n"
        : "+f"(c[0]), "+f"(c[1]), "+f"(c[2]), "+f"(c[3])
        : "r"(a[0]), "r"(a[1]), "r"(a[2]), "r"(a[3]), "r"(b[0]), "r"(b[1]));
}
__device__ __forceinline__ void cp16(const void* s, const void* g) {
    uint32_t sa = (uint32_t)__cvta_generic_to_shared(s);
    asm volatile("cp.async.cg.shared.global [%0], [%1], 16;\n" :: "r"(sa), "l"(g));
}
#define CPCOMMIT() asm volatile("cp.async.commit_group;\n" ::: "memory")
#define CPWAIT(n)  asm volatile("cp.async.wait_group %0;\n" :: "n"(n) : "memory")

// ---------------------------------------------------------------------------
// Weight -> fragment order (per (mb, 32k-stage): [kk(2)][mt(8)][lane(32)][q(4)])
// ---------------------------------------------------------------------------
__device__ __forceinline__ void wtrans_one(const float* __restrict__ w,
                                           __half* __restrict__ wf,
                                           int i, int K) {
    int m = i / K, k = i % K;
    int S = K >> 5;
    int mb = m >> 7, s = k >> 5;
    int kk = (k >> 4) & 1;
    int mt = (m >> 4) & 7;
    int r = m & 15, c = k & 15;
    int q = (r >> 3) | ((c >> 3) << 1);
    int lane = (r & 7) * 4 + ((c & 7) >> 1);
    size_t b32i = ((((size_t)(mb * S + s) * 2 + kk) * 8 + mt) * 32 + lane) * 4 + q;
    wf[b32i * 2 + (c & 1)] = __float2half_rn(w[i]);
}

#define WBLK ((C_MID * C_IN) / 256)    // 2304
#define EMBBLK ((2 * C_MID) / 8)       // 384
#define GNBLK (GROUPS * BATCH)         // 512

// ---------------------------------------------------------------------------
// Fused prep: w1 frags | w2 frags | emb GEMM | GroupNorm+xn, by block range.
// ---------------------------------------------------------------------------
__global__ void __launch_bounds__(256) prep(const float* __restrict__ w1,
                                            const float* __restrict__ w2,
                                            const float* __restrict__ emb,
                                            const float* __restrict__ we,
                                            const float* __restrict__ be,
                                            const float* __restrict__ x,
                                            const float* __restrict__ gn_w,
                                            const float* __restrict__ gn_b) {
    int bx = blockIdx.x;
    int t = threadIdx.x;
    if (bx < WBLK) {
        wtrans_one(w1, g_w1f, bx * 256 + t, C_IN);
        return;
    }
    if (bx < 2 * WBLK) {
        wtrans_one(w2, g_w2f, (bx - WBLK) * 256 + t, C_MID);
        return;
    }
    if (bx < 2 * WBLK + EMBBLK) {
        int w = t >> 5, lane = t & 31;
        int j = (bx - 2 * WBLK) * 8 + w;
        const float4* wrow = (const float4*)(we + (size_t)j * EMB_D);
        float4 wv[8];
#pragma unroll
        for (int i = 0; i < 8; i++) wv[i] = wrow[lane + 32 * i];
#pragma unroll
        for (int b = 0; b < BATCH; b++) {
            const float4* er = (const float4*)(emb + (size_t)b * EMB_D);
            float acc = 0.f;
#pragma unroll
            for (int i = 0; i < 8; i++) {
                float4 ev = __ldg(&er[lane + 32 * i]);
                acc += wv[i].x * ev.x + wv[i].y * ev.y + wv[i].z * ev.z + wv[i].w * ev.w;
            }
#pragma unroll
            for (int off = 16; off; off >>= 1) acc += __shfl_xor_sync(0xffffffffu, acc, off);
            if (lane == 0) g_embout[b * (2 * C_MID) + j] = acc + be[j];
        }
        return;
    }
    // ---- GroupNorm + xn ----
    int idx = bx - (2 * WBLK + EMBBLK);
    int g = idx & (GROUPS - 1), b = idx >> 5;
    const float* xp = x + ((size_t)b * C_IN + (size_t)g * CPG) * HW;
    const int N = CPG * HW;

    float s = 0.f, ss = 0.f;
    for (int i = t * 4; i < N; i += 256 * 4) {
        float4 v = *(const float4*)(xp + i);
        s  += v.x + v.y + v.z + v.w;
        ss += v.x * v.x + v.y * v.y + v.z * v.z + v.w * v.w;
    }
#pragma unroll
    for (int off = 16; off; off >>= 1) {
        s  += __shfl_xor_sync(0xffffffffu, s, off);
        ss += __shfl_xor_sync(0xffffffffu, ss, off);
    }
    __shared__ float rs[8], rss[8];
    if ((t & 31) == 0) { rs[t >> 5] = s; rss[t >> 5] = ss; }
    __syncthreads();
    __shared__ float smu, srst;
    if (t == 0) {
        float S = 0.f, SS = 0.f;
#pragma unroll
        for (int i = 0; i < 8; i++) { S += rs[i]; SS += rss[i]; }
        float mu  = S / (float)N;
        float var = SS / (float)N - mu * mu;
        smu = mu; srst = rsqrtf(var + EPSV);
    }
    __syncthreads();
    const float mu = smu, rst = srst;

    const int n4 = t * 4;
#pragma unroll
    for (int j = 0; j < CPG / 2; j++) {
        int c0 = g * CPG + j * 2;
        float a0 = rst * gn_w[c0],     b0 = gn_b[c0]     - mu * a0;
        float a1 = rst * gn_w[c0 + 1], b1 = gn_b[c0 + 1] - mu * a1;
        float4 x0 = *(const float4*)(x + ((size_t)b * C_IN + c0)     * HW + n4);
        float4 x1 = *(const float4*)(x + ((size_t)b * C_IN + c0 + 1) * HW + n4);
        uint4 o;
        o.x = packh(x0.x * a0 + b0, x1.x * a1 + b1);
        o.y = packh(x0.y * a0 + b0, x1.y * a1 + b1);
        o.z = packh(x0.z * a0 + b0, x1.z * a1 + b1);
        o.w = packh(x0.w * a0 + b0, x1.w * a1 + b1);
        *(uint4*)(g_xn + ((size_t)b * (C_IN / 2) + (c0 >> 1)) * HW + n4) = o;
    }
}

// ---------------------------------------------------------------------------
// fp16 m16n8k16 GEMM, 128x128 tile, 8 warps 2m x 4n, BK=64, NST=3, occ 2.
// EPI==1: silu+FiLM -> g_h fp16 pair-major. EPI==2: out = x + acc + b2.
// ---------------------------------------------------------------------------
template <int KTOT, int MTOT, int EPI>
__global__ void __launch_bounds__(256, 2) mma_gemm(
    const __half* __restrict__ Wf,
    const u32* __restrict__ Bsrc,
    const float* __restrict__ bias,
    const float* __restrict__ xres,
    float* __restrict__ outp)
{
    constexpr int BK   = 64;
    constexpr int NST  = 3;
    constexpr int KK   = BK / 16;
    constexpr int LDB  = 136;
    constexpr int A_U  = BM * BK / 2;       // 4096
    constexpr int B_U  = (BK / 2) * LDB;    // 4352
    constexpr int STG  = A_U + B_U;
    constexpr int S    = KTOT / BK;
    constexpr int MAXW = NST - 2;

    extern __shared__ float dsm[];
    u32* sm = (u32*)(((uintptr_t)dsm + 1023) & ~(uintptr_t)1023);

    const int t = threadIdx.x;
    const int b = blockIdx.z;
    const int m0 = blockIdx.x * BM;
    const int p0 = blockIdx.y * 128;
    const int wid = t >> 5, lane = t & 31;
    const int gr = lane >> 2, tg = lane & 3;
    const int mtb = (wid >> 2) * 4;
    const int nw = (wid & 3) * 32;

    const u32* Wb = (const u32*)Wf + (size_t)blockIdx.x * (KTOT / 32) * 2048;
    const u32* Bb = Bsrc + (size_t)b * (KTOT / 2) * HW + p0;

    float acc[4][4][4];
#pragma unroll
    for (int i = 0; i < 4; i++)
#pragma unroll
        for (int j = 0; j < 4; j++)
#pragma unroll
            for (int q = 0; q < 4; q++) acc[i][j][q] = 0.f;

    auto fill = [&](int st) {
        u32* sA = sm + (st % NST) * STG;
        u32* sB = sA + A_U;
        const u32* gA = Wb + (size_t)st * A_U;
#pragma unroll
        for (int it = 0; it < A_U / 1024; it++)
            cp16(sA + it * 1024 + t * 4, gA + it * 1024 + t * 4);
#pragma unroll
        for (int it = 0; it < BK / 16; it++) {
            int idx = t + it * 256;
            int row = idx >> 5, c4 = (idx & 31) * 4;
            cp16(sB + row * LDB + c4, Bb + (size_t)(st * (BK / 2) + row) * HW + c4);
        }
        CPCOMMIT();
    };

#pragma unroll
    for (int p = 0; p < NST - 1; p++) fill(p);

    for (int s = 0; s < S; s++) {
        const int rem = S - 1 - s;
        if (MAXW >= 1 && rem >= 1) { CPWAIT(1); } else { CPWAIT(0); }
        __syncthreads();
        if (s + NST - 1 < S) fill(s + NST - 1);

        const u32* sA = sm + (s % NST) * STG;
        const u32* sB = sA + A_U;

#pragma unroll
        for (int kk = 0; kk < KK; kk++) {
            u32 af[4][4];
#pragma unroll
            for (int mi = 0; mi < 4; mi++) {
                const uint4 v = *(const uint4*)(sA + ((kk * 8 + mtb + mi) * 32 + lane) * 4);
                af[mi][0] = v.x; af[mi][1] = v.y; af[mi][2] = v.z; af[mi][3] = v.w;
            }
            u32 bf[4][2];
#pragma unroll
            for (int ni = 0; ni < 4; ni++) {
                int nc = nw + ni * 8 + gr;
                bf[ni][0] = sB[(kk * 8 + tg)     * LDB + nc];
                bf[ni][1] = sB[(kk * 8 + tg + 4) * LDB + nc];
            }
#pragma unroll
            for (int mi = 0; mi < 4; mi++)
#pragma unroll
                for (int ni = 0; ni < 4; ni++)
                    mma16(acc[mi][ni], af[mi], bf[ni]);
        }
    }
    __syncthreads();

    // ---------------- epilogue ----------------
    if (EPI == 1) {
        float* tile = (float*)sm;
        const float* sc = g_embout + b * 2 * C_MID;
#pragma unroll
        for (int mi = 0; mi < 4; mi++) {
#pragma unroll
            for (int half = 0; half < 2; half++) {
                int rl = (mtb + mi) * 16 + gr + half * 8;
                int r = m0 + rl;
                float bi    = bias[r];
                float scale = 1.f + sc[r];
                float shift = sc[C_MID + r];
#pragma unroll
                for (int ni = 0; ni < 4; ni++) {
                    float v0 = acc[mi][ni][half * 2]     + bi;
                    float v1 = acc[mi][ni][half * 2 + 1] + bi;
                    v0 = v0 / (1.f + __expf(-v0));
                    v1 = v1 / (1.f + __expf(-v1));
                    float2 o = make_float2(v0 * scale + shift, v1 * scale + shift);
                    *(float2*)(tile + rl * LDT + nw + ni * 8 + tg * 2) = o;
                }
            }
        }
        __syncthreads();
#pragma unroll
        for (int it = 0; it < 8; it++) {
            int idx = t + it * 256;
            int p = idx >> 5, c4 = (idx & 31) * 4;
            const float* r0 = tile + (2 * p)     * LDT + c4;
            const float* r1 = tile + (2 * p + 1) * LDT + c4;
            uint4 o;
            o.x = packh(r0[0], r1[0]);
            o.y = packh(r0[1], r1[1]);
            o.z = packh(r0[2], r1[2]);
            o.w = packh(r0[3], r1[3]);
            *(uint4*)(g_h + ((size_t)b * (C_MID / 2) + (m0 >> 1) + p) * HW + p0 + c4) = o;
        }
    } else {
#pragma unroll
        for (int mi = 0; mi < 4; mi++) {
#pragma unroll
            for (int half = 0; half < 2; half++) {
                int r = m0 + (mtb + mi) * 16 + gr + half * 8;
                float bi = bias[r];
                const float* xrow = xres + ((size_t)b * C_IN + r) * HW + p0 + nw;
                float* orow = outp + ((size_t)b * C_IN + r) * HW + p0 + nw;
#pragma unroll
                for (int ni = 0; ni < 4; ni++) {
                    float2 xv = *(const float2*)(xrow + ni * 8 + tg * 2);
                    float2 o = make_float2(xv.x + acc[mi][ni][half * 2]     + bi,
                                           xv.y + acc[mi][ni][half * 2 + 1] + bi);
                    *(float2*)(orow + ni * 8 + tg * 2) = o;
                }
            }
        }
    }
}

// ---------------------------------------------------------------------------
extern "C" void kernel_launch(void* const* d_in, const int* in_sizes, int n_in,
                              void* d_out, int out_size) {
    const float* x    = (const float*)d_in[0];
    const float* emb  = (const float*)d_in[1];
    const float* gn_w = (const float*)d_in[2];
    const float* gn_b = (const float*)d_in[3];
    const float* w1   = (const float*)d_in[4];
    const float* b1   = (const float*)d_in[5];
    const float* we   = (const float*)d_in[6];
    const float* be   = (const float*)d_in[7];
    const float* w2   = (const float*)d_in[8];
    const float* b2   = (const float*)d_in[9];
    float* out = (float*)d_out;

    u32 *hbuf, *xnbuf;
    __half *w1f, *w2f;
    cudaGetSymbolAddress((void**)&hbuf, g_h);
    cudaGetSymbolAddress((void**)&xnbuf, g_xn);
    cudaGetSymbolAddress((void**)&w1f, g_w1f);
    cudaGetSymbolAddress((void**)&w2f, g_w2f);

    // BK=64, NST=3: stage = 4096 + 32*136 = 8448 u32 -> 101,376 B + align
    constexpr int SMEMB = 3 * (4096 + 32 * 136) * 4 + 1024;

    cudaFuncSetAttribute((const void*)mma_gemm<C_IN, C_MID, 1>,
                         cudaFuncAttributeMaxDynamicSharedMemorySize, SMEMB);
    cudaFuncSetAttribute((const void*)mma_gemm<C_MID, C_IN, 2>,
                         cudaFuncAttributeMaxDynamicSharedMemorySize, SMEMB);

    prep<<<2 * WBLK + EMBBLK + GNBLK, 256>>>(w1, w2, emb, we, be, x, gn_w, gn_b);

    mma_gemm<C_IN, C_MID, 1><<<dim3(C_MID / BM, HW / 128, BATCH), 256, SMEMB>>>(
        w1f, xnbuf, b1, nullptr, nullptr);
    mma_gemm<C_MID, C_IN, 2><<<dim3(C_IN / BM, HW / 128, BATCH), 256, SMEMB>>>(
        w2f, hbuf, b2, x, out);
}

// round 14
// speedup vs baseline: 1.1082x; 1.0454x over previous
#include <cuda_runtime.h>
#include <cuda_fp16.h>
#include <math.h>
#include <stdint.h>

#define C_IN   384
#define C_MID  1536
#define EMB_D  1024
#define BATCH  16
#define HW     1024
#define GROUPS 32
#define CPG    12
#define EPSV   1e-5f

#define BM 128
#define LDT 132

typedef unsigned int u32;

// ---------------- device scratch ----------------
__device__ u32 g_h[(size_t)BATCH * (C_MID / 2) * HW];   // h fp16 pair-major
__device__ u32 g_xn[(size_t)BATCH * (C_IN / 2) * HW];   // xn fp16 pair-major
__device__ float g_embout[BATCH * 2 * C_MID];
__device__ __half g_w1f[C_MID * C_IN];
__device__ __half g_w2f[C_IN * C_MID];

// ---------------- helpers ----------------
__device__ __forceinline__ u32 packh(float lo, float hi) {
    __half2 h = __floats2half2_rn(lo, hi);
    return *(u32*)&h;
}
__device__ __forceinline__ void mma16(float* c, const u32* a, const u32* b) {
    asm volatile(
        "mma.sync.aligned.m16n8k16.row.col.f32.f16.f16.f32 "
        "{%0,%1,%2,%3}, {%4,%5,%6,%7}, {%8,%9}, {%0,%1,%2,%3};\n"
        : "+f"(c[0]), "+f"(c[1]), "+f"(c[2]), "+f"(c[3])
        : "r"(a[0]), "r"(a[1]), "r"(a[2]), "r"(a[3]), "r"(b[0]), "r"(b[1]));
}
__device__ __forceinline__ void cp16(const void* s, const void* g) {
    uint32_t sa = (uint32_t)__cvta_generic_to_shared(s);
    asm volatile("cp.async.cg.shared.global [%0], [%1], 16;\n" :: "r"(sa), "l"(g));
}
#define CPCOMMIT() asm volatile("cp.async.commit_group;\n" ::: "memory")
#define CPWAIT(n)  asm volatile("cp.async.wait_group %0;\n" :: "n"(n) : "memory")

// ---------------------------------------------------------------------------
// Vectorized weight -> fragment order. One thread: 4 consecutive k of one m.
// Layout per (mb, 32k-stage): [kk(2)][mt(8)][lane(32)][q(4)] u32.
// For k0 % 4 == 0: q and (c>>3) constant over the 4 elems; lanes l, l+1 take
// packh(v.x,v.y), packh(v.z,v.w).
// ---------------------------------------------------------------------------
__device__ __forceinline__ void wtrans4(const float* __restrict__ w,
                                        __half* __restrict__ wf,
                                        int i4, int K) {
    int m = (i4 * 4) / K, k0 = (i4 * 4) % K;
    float4 v = *(const float4*)(w + (size_t)m * K + k0);
    int S = K >> 5;
    int mb = m >> 7, s = k0 >> 5;
    int kk = (k0 >> 4) & 1;
    int mt = (m >> 4) & 7;
    int r = m & 15, c0 = k0 & 15;
    int q = (r >> 3) | ((c0 >> 3) << 1);
    int lane0 = (r & 7) * 4 + ((c0 & 7) >> 1);
    u32* wfu = (u32*)wf;
    size_t base = ((((size_t)(mb * S + s) * 2 + kk) * 8 + mt) * 32) * 4 + q;
    wfu[base + (size_t)lane0 * 4]       = packh(v.x, v.y);
    wfu[base + (size_t)(lane0 + 1) * 4] = packh(v.z, v.w);
}

#define W4BLK ((C_MID * C_IN / 4) / 256)   // 576 blocks per weight
#define EMBBLK ((2 * C_MID) / 8)           // 384
#define GNBLK (GROUPS * BATCH)             // 512
#define GN_SMEM (CPG * HW * 4)             // 49152 B

// ---------------------------------------------------------------------------
// Fused prep: GroupNorm+xn (first: long pole) | w1 | w2 | emb GEMM.
// ---------------------------------------------------------------------------
__global__ void __launch_bounds__(256) prep(const float* __restrict__ w1,
                                            const float* __restrict__ w2,
                                            const float* __restrict__ emb,
                                            const float* __restrict__ we,
                                            const float* __restrict__ be,
                                            const float* __restrict__ x,
                                            const float* __restrict__ gn_w,
                                            const float* __restrict__ gn_b) {
    extern __shared__ float xs[];
    int bx = blockIdx.x;
    int t = threadIdx.x;

    if (bx < GNBLK) {
        // ---- GroupNorm + xn, single DRAM pass via smem staging ----
        int g = bx & (GROUPS - 1), b = bx >> 5;
        const float4* xp4 = (const float4*)(x + ((size_t)b * C_IN + (size_t)g * CPG) * HW);
#pragma unroll
        for (int it = 0; it < 12; it++)
            cp16(&xs[(t + it * 256) * 4], &xp4[t + it * 256]);
        CPCOMMIT(); CPWAIT(0);
        __syncthreads();

        float s = 0.f, ss = 0.f;
#pragma unroll
        for (int it = 0; it < 12; it++) {
            float4 v = *(const float4*)&xs[(t + it * 256) * 4];
            s  += v.x + v.y + v.z + v.w;
            ss += v.x * v.x + v.y * v.y + v.z * v.z + v.w * v.w;
        }
#pragma unroll
        for (int off = 16; off; off >>= 1) {
            s  += __shfl_xor_sync(0xffffffffu, s, off);
            ss += __shfl_xor_sync(0xffffffffu, ss, off);
        }
        __shared__ float rs[8], rss[8];
        if ((t & 31) == 0) { rs[t >> 5] = s; rss[t >> 5] = ss; }
        __syncthreads();
        __shared__ float smu, srst;
        if (t == 0) {
            const int N = CPG * HW;
            float S = 0.f, SS = 0.f;
#pragma unroll
            for (int i = 0; i < 8; i++) { S += rs[i]; SS += rss[i]; }
            float mu  = S / (float)N;
            float var = SS / (float)N - mu * mu;
            smu = mu; srst = rsqrtf(var + EPSV);
        }
        __syncthreads();
        const float mu = smu, rst = srst;

        const int n4 = t * 4;
#pragma unroll
        for (int j = 0; j < CPG / 2; j++) {
            int c0 = g * CPG + j * 2;
            float a0 = rst * gn_w[c0],     b0 = gn_b[c0]     - mu * a0;
            float a1 = rst * gn_w[c0 + 1], b1 = gn_b[c0 + 1] - mu * a1;
            float4 x0 = *(const float4*)&xs[(2 * j)     * HW + n4];
            float4 x1 = *(const float4*)&xs[(2 * j + 1) * HW + n4];
            uint4 o;
            o.x = packh(x0.x * a0 + b0, x1.x * a1 + b1);
            o.y = packh(x0.y * a0 + b0, x1.y * a1 + b1);
            o.z = packh(x0.z * a0 + b0, x1.z * a1 + b1);
            o.w = packh(x0.w * a0 + b0, x1.w * a1 + b1);
            *(uint4*)(g_xn + ((size_t)b * (C_IN / 2) + (c0 >> 1)) * HW + n4) = o;
        }
        return;
    }
    bx -= GNBLK;
    if (bx < W4BLK) {
        wtrans4(w1, g_w1f, bx * 256 + t, C_IN);
        return;
    }
    if (bx < 2 * W4BLK) {
        wtrans4(w2, g_w2f, (bx - W4BLK) * 256 + t, C_MID);
        return;
    }
    // ---- emb GEMM ----
    int w = t >> 5, lane = t & 31;
    int j = (bx - 2 * W4BLK) * 8 + w;
    const float4* wrow = (const float4*)(we + (size_t)j * EMB_D);
    float4 wv[8];
#pragma unroll
    for (int i = 0; i < 8; i++) wv[i] = wrow[lane + 32 * i];
#pragma unroll
    for (int b = 0; b < BATCH; b++) {
        const float4* er = (const float4*)(emb + (size_t)b * EMB_D);
        float acc = 0.f;
#pragma unroll
        for (int i = 0; i < 8; i++) {
            float4 ev = __ldg(&er[lane + 32 * i]);
            acc += wv[i].x * ev.x + wv[i].y * ev.y + wv[i].z * ev.z + wv[i].w * ev.w;
        }
#pragma unroll
        for (int off = 16; off; off >>= 1) acc += __shfl_xor_sync(0xffffffffu, acc, off);
        if (lane == 0) g_embout[b * (2 * C_MID) + j] = acc + be[j];
    }
}

// ---------------------------------------------------------------------------
// fp16 m16n8k16 GEMM, 128x128 tile, 8 warps 2m x 4n, BK=64, NST=3, occ 2.
// EPI==1: silu+FiLM -> g_h fp16 pair-major. EPI==2: out = x + acc + b2.
// ---------------------------------------------------------------------------
template <int KTOT, int MTOT, int EPI>
__global__ void __launch_bounds__(256, 2) mma_gemm(
    const __half* __restrict__ Wf,
    const u32* __restrict__ Bsrc,
    const float* __restrict__ bias,
    const float* __restrict__ xres,
    float* __restrict__ outp)
{
    constexpr int BK   = 64;
    constexpr int NST  = 3;
    constexpr int KK   = BK / 16;
    constexpr int LDB  = 136;
    constexpr int A_U  = BM * BK / 2;       // 4096
    constexpr int B_U  = (BK / 2) * LDB;    // 4352
    constexpr int STG  = A_U + B_U;
    constexpr int S    = KTOT / BK;

    extern __shared__ float dsm[];
    u32* sm = (u32*)(((uintptr_t)dsm + 1023) & ~(uintptr_t)1023);

    const int t = threadIdx.x;
    const int b = blockIdx.z;
    const int m0 = blockIdx.x * BM;
    const int p0 = blockIdx.y * 128;
    const int wid = t >> 5, lane = t & 31;
    const int gr = lane >> 2, tg = lane & 3;
    const int mtb = (wid >> 2) * 4;
    const int nw = (wid & 3) * 32;

    const u32* Wb = (const u32*)Wf + (size_t)blockIdx.x * (KTOT / 32) * 2048;
    const u32* Bb = Bsrc + (size_t)b * (KTOT / 2) * HW + p0;

    float acc[4][4][4];
#pragma unroll
    for (int i = 0; i < 4; i++)
#pragma unroll
        for (int j = 0; j < 4; j++)
#pragma unroll
            for (int q = 0; q < 4; q++) acc[i][j][q] = 0.f;

    auto fill = [&](int st) {
        u32* sA = sm + (st % NST) * STG;
        u32* sB = sA + A_U;
        const u32* gA = Wb + (size_t)st * A_U;
#pragma unroll
        for (int it = 0; it < A_U / 1024; it++)
            cp16(sA + it * 1024 + t * 4, gA + it * 1024 + t * 4);
#pragma unroll
        for (int it = 0; it < BK / 16; it++) {
            int idx = t + it * 256;
            int row = idx >> 5, c4 = (idx & 31) * 4;
            cp16(sB + row * LDB + c4, Bb + (size_t)(st * (BK / 2) + row) * HW + c4);
        }
        CPCOMMIT();
    };

#pragma unroll
    for (int p = 0; p < NST - 1; p++) fill(p);

    for (int s = 0; s < S; s++) {
        if (S - 1 - s >= 1) { CPWAIT(1); } else { CPWAIT(0); }
        __syncthreads();
        if (s + NST - 1 < S) fill(s + NST - 1);

        const u32* sA = sm + (s % NST) * STG;
        const u32* sB = sA + A_U;

#pragma unroll
        for (int kk = 0; kk < KK; kk++) {
            u32 af[4][4];
#pragma unroll
            for (int mi = 0; mi < 4; mi++) {
                const uint4 v = *(const uint4*)(sA + ((kk * 8 + mtb + mi) * 32 + lane) * 4);
                af[mi][0] = v.x; af[mi][1] = v.y; af[mi][2] = v.z; af[mi][3] = v.w;
            }
            u32 bf[4][2];
#pragma unroll
            for (int ni = 0; ni < 4; ni++) {
                int nc = nw + ni * 8 + gr;
                bf[ni][0] = sB[(kk * 8 + tg)     * LDB + nc];
                bf[ni][1] = sB[(kk * 8 + tg + 4) * LDB + nc];
            }
#pragma unroll
            for (int mi = 0; mi < 4; mi++)
#pragma unroll
                for (int ni = 0; ni < 4; ni++)
                    mma16(acc[mi][ni], af[mi], bf[ni]);
        }
    }
    __syncthreads();

    // ---------------- epilogue ----------------
    if (EPI == 1) {
        float* tile = (float*)sm;
        const float* sc = g_embout + b * 2 * C_MID;
#pragma unroll
        for (int mi = 0; mi < 4; mi++) {
#pragma unroll
            for (int half = 0; half < 2; half++) {
                int rl = (mtb + mi) * 16 + gr + half * 8;
                int r = m0 + rl;
                float bi    = bias[r];
                float scale = 1.f + sc[r];
                float shift = sc[C_MID + r];
#pragma unroll
                for (int ni = 0; ni < 4; ni++) {
                    float v0 = acc[mi][ni][half * 2]     + bi;
                    float v1 = acc[mi][ni][half * 2 + 1] + bi;
                    v0 = v0 / (1.f + __expf(-v0));
                    v1 = v1 / (1.f + __expf(-v1));
                    float2 o = make_float2(v0 * scale + shift, v1 * scale + shift);
                    *(float2*)(tile + rl * LDT + nw + ni * 8 + tg * 2) = o;
                }
            }
        }
        __syncthreads();
#pragma unroll
        for (int it = 0; it < 8; it++) {
            int idx = t + it * 256;
            int p = idx >> 5, c4 = (idx & 31) * 4;
            const float* r0 = tile + (2 * p)     * LDT + c4;
            const float* r1 = tile + (2 * p + 1) * LDT + c4;
            uint4 o;
            o.x = packh(r0[0], r1[0]);
            o.y = packh(r0[1], r1[1]);
            o.z = packh(r0[2], r1[2]);
            o.w = packh(r0[3], r1[3]);
            *(uint4*)(g_h + ((size_t)b * (C_MID / 2) + (m0 >> 1) + p) * HW + p0 + c4) = o;
        }
    } else {
#pragma unroll
        for (int mi = 0; mi < 4; mi++) {
#pragma unroll
            for (int half = 0; half < 2; half++) {
                int r = m0 + (mtb + mi) * 16 + gr + half * 8;
                float bi = bias[r];
                const float* xrow = xres + ((size_t)b * C_IN + r) * HW + p0 + nw;
                float* orow = outp + ((size_t)b * C_IN + r) * HW + p0 + nw;
#pragma unroll
                for (int ni = 0; ni < 4; ni++) {
                    float2 xv = *(const float2*)(xrow + ni * 8 + tg * 2);
                    float2 o = make_float2(xv.x + acc[mi][ni][half * 2]     + bi,
                                           xv.y + acc[mi][ni][half * 2 + 1] + bi);
                    *(float2*)(orow + ni * 8 + tg * 2) = o;
                }
            }
        }
    }
}

// ---------------------------------------------------------------------------
extern "C" void kernel_launch(void* const* d_in, const int* in_sizes, int n_in,
                              void* d_out, int out_size) {
    const float* x    = (const float*)d_in[0];
    const float* emb  = (const float*)d_in[1];
    const float* gn_w = (const float*)d_in[2];
    const float* gn_b = (const float*)d_in[3];
    const float* w1   = (const float*)d_in[4];
    const float* b1   = (const float*)d_in[5];
    const float* we   = (const float*)d_in[6];
    const float* be   = (const float*)d_in[7];
    const float* w2   = (const float*)d_in[8];
    const float* b2   = (const float*)d_in[9];
    float* out = (float*)d_out;

    u32 *hbuf, *xnbuf;
    __half *w1f, *w2f;
    cudaGetSymbolAddress((void**)&hbuf, g_h);
    cudaGetSymbolAddress((void**)&xnbuf, g_xn);
    cudaGetSymbolAddress((void**)&w1f, g_w1f);
    cudaGetSymbolAddress((void**)&w2f, g_w2f);

    constexpr int SMEMB = 3 * (4096 + 32 * 136) * 4 + 1024;

    cudaFuncSetAttribute((const void*)prep,
                         cudaFuncAttributeMaxDynamicSharedMemorySize, GN_SMEM);
    cudaFuncSetAttribute((const void*)mma_gemm<C_IN, C_MID, 1>,
                         cudaFuncAttributeMaxDynamicSharedMemorySize, SMEMB);
    cudaFuncSetAttribute((const void*)mma_gemm<C_MID, C_IN, 2>,
                         cudaFuncAttributeMaxDynamicSharedMemorySize, SMEMB);

    prep<<<GNBLK + 2 * W4BLK + EMBBLK, 256, GN_SMEM>>>(
        w1, w2, emb, we, be, x, gn_w, gn_b);

    mma_gemm<C_IN, C_MID, 1><<<dim3(C_MID / BM, HW / 128, BATCH), 256, SMEMB>>>(
        w1f, xnbuf, b1, nullptr, nullptr);
    mma_gemm<C_MID, C_IN, 2><<<dim3(C_IN / BM, HW / 128, BATCH), 256, SMEMB>>>(
        w2f, hbuf, b2, x, out);
}

// round 15
// speedup vs baseline: 1.1107x; 1.0023x over previous
#include <cuda_runtime.h>
#include <cuda_fp16.h>
#include <math.h>
#include <stdint.h>

#define C_IN   384
#define C_MID  1536
#define EMB_D  1024
#define BATCH  16
#define HW     1024
#define GROUPS 32
#define CPG    12
#define EPSV   1e-5f

#define BM 128
#define LDT 132

typedef unsigned int u32;

// ---------------- device scratch ----------------
__device__ u32 g_h[(size_t)BATCH * (C_MID / 2) * HW];   // h fp16 pair-major
__device__ u32 g_xn[(size_t)BATCH * (C_IN / 2) * HW];   // xn fp16 pair-major
__device__ float g_embout[BATCH * 2 * C_MID];
__device__ __half g_w1f[C_MID * C_IN];
__device__ __half g_w2f[C_IN * C_MID];

// ---------------- helpers ----------------
__device__ __forceinline__ u32 packh(float lo, float hi) {
    __half2 h = __floats2half2_rn(lo, hi);
    return *(u32*)&h;
}
__device__ __forceinline__ void mma16(float* c, const u32* a, const u32* b) {
    asm volatile(
        "mma.sync.aligned.m16n8k16.row.col.f32.f16.f16.f32 "
        "{%0,%1,%2,%3}, {%4,%5,%6,%7}, {%8,%9}, {%0,%1,%2,%3};\n"
        : "+f"(c[0]), "+f"(c[1]), "+f"(c[2]), "+f"(c[3])
        : "r"(a[0]), "r"(a[1]), "r"(a[2]), "r"(a[3]), "r"(b[0]), "r"(b[1]));
}
__device__ __forceinline__ void cp16(const void* s, const void* g) {
    uint32_t sa = (uint32_t)__cvta_generic_to_shared(s);
    asm volatile("cp.async.cg.shared.global [%0], [%1], 16;\n" :: "r"(sa), "l"(g));
}
#define CPCOMMIT() asm volatile("cp.async.commit_group;\n" ::: "memory")
#define CPWAIT(n)  asm volatile("cp.async.wait_group %0;\n" :: "n"(n) : "memory")

// ---------------------------------------------------------------------------
// Vectorized weight -> fragment order (one thread: 4 consecutive k of one m).
// ---------------------------------------------------------------------------
__device__ __forceinline__ void wtrans4(const float* __restrict__ w,
                                        __half* __restrict__ wf,
                                        int i4, int K) {
    int m = (i4 * 4) / K, k0 = (i4 * 4) % K;
    float4 v = *(const float4*)(w + (size_t)m * K + k0);
    int S = K >> 5;
    int mb = m >> 7, s = k0 >> 5;
    int kk = (k0 >> 4) & 1;
    int mt = (m >> 4) & 7;
    int r = m & 15, c0 = k0 & 15;
    int q = (r >> 3) | ((c0 >> 3) << 1);
    int lane0 = (r & 7) * 4 + ((c0 & 7) >> 1);
    u32* wfu = (u32*)wf;
    size_t base = ((((size_t)(mb * S + s) * 2 + kk) * 8 + mt) * 32) * 4 + q;
    wfu[base + (size_t)lane0 * 4]       = packh(v.x, v.y);
    wfu[base + (size_t)(lane0 + 1) * 4] = packh(v.z, v.w);
}

#define W4BLK ((C_MID * C_IN / 4) / 256)   // 576 blocks per weight
#define EMBBLK ((2 * C_MID) / 8)           // 384
#define GNBLK (GROUPS * BATCH)             // 512

// ---------------------------------------------------------------------------
// Fused prep: GroupNorm+xn (register-resident) | w1 | w2 | emb GEMM.
// No dynamic smem -> full occupancy for all block ranges.
// ---------------------------------------------------------------------------
__global__ void __launch_bounds__(256) prep(const float* __restrict__ w1,
                                            const float* __restrict__ w2,
                                            const float* __restrict__ emb,
                                            const float* __restrict__ we,
                                            const float* __restrict__ be,
                                            const float* __restrict__ x,
                                            const float* __restrict__ gn_w,
                                            const float* __restrict__ gn_b) {
    int bx = blockIdx.x;
    int t = threadIdx.x;

    if (bx < GNBLK) {
        // ---- GroupNorm + xn, single pass, data held in registers ----
        // thread t, slot it: channel it of the group, positions t*4 .. t*4+3
        int g = bx & (GROUPS - 1), b = bx >> 5;
        const float4* xp4 = (const float4*)(x + ((size_t)b * C_IN + (size_t)g * CPG) * HW);
        float4 xv[CPG];
#pragma unroll
        for (int it = 0; it < CPG; it++)
            xv[it] = __ldg(&xp4[t + it * 256]);

        float s = 0.f, ss = 0.f;
#pragma unroll
        for (int it = 0; it < CPG; it++) {
            float4 v = xv[it];
            s  += v.x + v.y + v.z + v.w;
            ss += v.x * v.x + v.y * v.y + v.z * v.z + v.w * v.w;
        }
#pragma unroll
        for (int off = 16; off; off >>= 1) {
            s  += __shfl_xor_sync(0xffffffffu, s, off);
            ss += __shfl_xor_sync(0xffffffffu, ss, off);
        }
        __shared__ float rs[8], rss[8];
        if ((t & 31) == 0) { rs[t >> 5] = s; rss[t >> 5] = ss; }
        __syncthreads();
        __shared__ float smu, srst;
        if (t == 0) {
            const int N = CPG * HW;
            float S = 0.f, SS = 0.f;
#pragma unroll
            for (int i = 0; i < 8; i++) { S += rs[i]; SS += rss[i]; }
            float mu  = S / (float)N;
            float var = SS / (float)N - mu * mu;
            smu = mu; srst = rsqrtf(var + EPSV);
        }
        __syncthreads();
        const float mu = smu, rst = srst;

        const int n4 = t * 4;
#pragma unroll
        for (int j = 0; j < CPG / 2; j++) {
            int c0 = g * CPG + j * 2;
            float a0 = rst * gn_w[c0],     b0 = gn_b[c0]     - mu * a0;
            float a1 = rst * gn_w[c0 + 1], b1 = gn_b[c0 + 1] - mu * a1;
            float4 x0 = xv[2 * j];
            float4 x1 = xv[2 * j + 1];
            uint4 o;
            o.x = packh(x0.x * a0 + b0, x1.x * a1 + b1);
            o.y = packh(x0.y * a0 + b0, x1.y * a1 + b1);
            o.z = packh(x0.z * a0 + b0, x1.z * a1 + b1);
            o.w = packh(x0.w * a0 + b0, x1.w * a1 + b1);
            *(uint4*)(g_xn + ((size_t)b * (C_IN / 2) + (c0 >> 1)) * HW + n4) = o;
        }
        return;
    }
    bx -= GNBLK;
    if (bx < W4BLK) {
        wtrans4(w1, g_w1f, bx * 256 + t, C_IN);
        return;
    }
    if (bx < 2 * W4BLK) {
        wtrans4(w2, g_w2f, (bx - W4BLK) * 256 + t, C_MID);
        return;
    }
    // ---- emb GEMM ----
    int w = t >> 5, lane = t & 31;
    int j = (bx - 2 * W4BLK) * 8 + w;
    const float4* wrow = (const float4*)(we + (size_t)j * EMB_D);
    float4 wv[8];
#pragma unroll
    for (int i = 0; i < 8; i++) wv[i] = wrow[lane + 32 * i];
#pragma unroll
    for (int b = 0; b < BATCH; b++) {
        const float4* er = (const float4*)(emb + (size_t)b * EMB_D);
        float acc = 0.f;
#pragma unroll
        for (int i = 0; i < 8; i++) {
            float4 ev = __ldg(&er[lane + 32 * i]);
            acc += wv[i].x * ev.x + wv[i].y * ev.y + wv[i].z * ev.z + wv[i].w * ev.w;
        }
#pragma unroll
        for (int off = 16; off; off >>= 1) acc += __shfl_xor_sync(0xffffffffu, acc, off);
        if (lane == 0) g_embout[b * (2 * C_MID) + j] = acc + be[j];
    }
}

// ---------------------------------------------------------------------------
// fp16 m16n8k16 GEMM, 128x128 tile, 8 warps 2m x 4n, BK=64, NST=3, occ 2.
// EPI==1: silu+FiLM -> g_h fp16 pair-major. EPI==2: out = x + acc + b2.
// ---------------------------------------------------------------------------
template <int KTOT, int MTOT, int EPI>
__global__ void __launch_bounds__(256, 2) mma_gemm(
    const __half* __restrict__ Wf,
    const u32* __restrict__ Bsrc,
    const float* __restrict__ bias,
    const float* __restrict__ xres,
    float* __restrict__ outp)
{
    constexpr int BK   = 64;
    constexpr int NST  = 3;
    constexpr int KK   = BK / 16;
    constexpr int LDB  = 136;
    constexpr int A_U  = BM * BK / 2;       // 4096
    constexpr int B_U  = (BK / 2) * LDB;    // 4352
    constexpr int STG  = A_U + B_U;
    constexpr int S    = KTOT / BK;

    extern __shared__ float dsm[];
    u32* sm = (u32*)(((uintptr_t)dsm + 1023) & ~(uintptr_t)1023);

    const int t = threadIdx.x;
    const int b = blockIdx.z;
    const int m0 = blockIdx.x * BM;
    const int p0 = blockIdx.y * 128;
    const int wid = t >> 5, lane = t & 31;
    const int gr = lane >> 2, tg = lane & 3;
    const int mtb = (wid >> 2) * 4;
    const int nw = (wid & 3) * 32;

    const u32* Wb = (const u32*)Wf + (size_t)blockIdx.x * (KTOT / 32) * 2048;
    const u32* Bb = Bsrc + (size_t)b * (KTOT / 2) * HW + p0;

    float acc[4][4][4];
#pragma unroll
    for (int i = 0; i < 4; i++)
#pragma unroll
        for (int j = 0; j < 4; j++)
#pragma unroll
            for (int q = 0; q < 4; q++) acc[i][j][q] = 0.f;

    auto fill = [&](int st) {
        u32* sA = sm + (st % NST) * STG;
        u32* sB = sA + A_U;
        const u32* gA = Wb + (size_t)st * A_U;
#pragma unroll
        for (int it = 0; it < A_U / 1024; it++)
            cp16(sA + it * 1024 + t * 4, gA + it * 1024 + t * 4);
#pragma unroll
        for (int it = 0; it < BK / 16; it++) {
            int idx = t + it * 256;
            int row = idx >> 5, c4 = (idx & 31) * 4;
            cp16(sB + row * LDB + c4, Bb + (size_t)(st * (BK / 2) + row) * HW + c4);
        }
        CPCOMMIT();
    };

#pragma unroll
    for (int p = 0; p < NST - 1; p++) fill(p);

    for (int s = 0; s < S; s++) {
        if (S - 1 - s >= 1) { CPWAIT(1); } else { CPWAIT(0); }
        __syncthreads();
        if (s + NST - 1 < S) fill(s + NST - 1);

        const u32* sA = sm + (s % NST) * STG;
        const u32* sB = sA + A_U;

#pragma unroll
        for (int kk = 0; kk < KK; kk++) {
            u32 af[4][4];
#pragma unroll
            for (int mi = 0; mi < 4; mi++) {
                const uint4 v = *(const uint4*)(sA + ((kk * 8 + mtb + mi) * 32 + lane) * 4);
                af[mi][0] = v.x; af[mi][1] = v.y; af[mi][2] = v.z; af[mi][3] = v.w;
            }
            u32 bf[4][2];
#pragma unroll
            for (int ni = 0; ni < 4; ni++) {
                int nc = nw + ni * 8 + gr;
                bf[ni][0] = sB[(kk * 8 + tg)     * LDB + nc];
                bf[ni][1] = sB[(kk * 8 + tg + 4) * LDB + nc];
            }
#pragma unroll
            for (int mi = 0; mi < 4; mi++)
#pragma unroll
                for (int ni = 0; ni < 4; ni++)
                    mma16(acc[mi][ni], af[mi], bf[ni]);
        }
    }
    __syncthreads();

    // ---------------- epilogue ----------------
    if (EPI == 1) {
        float* tile = (float*)sm;
        const float* sc = g_embout + b * 2 * C_MID;
#pragma unroll
        for (int mi = 0; mi < 4; mi++) {
#pragma unroll
            for (int half = 0; half < 2; half++) {
                int rl = (mtb + mi) * 16 + gr + half * 8;
                int r = m0 + rl;
                float bi    = bias[r];
                float scale = 1.f + sc[r];
                float shift = sc[C_MID + r];
#pragma unroll
                for (int ni = 0; ni < 4; ni++) {
                    float v0 = acc[mi][ni][half * 2]     + bi;
                    float v1 = acc[mi][ni][half * 2 + 1] + bi;
                    v0 = v0 / (1.f + __expf(-v0));
                    v1 = v1 / (1.f + __expf(-v1));
                    float2 o = make_float2(v0 * scale + shift, v1 * scale + shift);
                    *(float2*)(tile + rl * LDT + nw + ni * 8 + tg * 2) = o;
                }
            }
        }
        __syncthreads();
#pragma unroll
        for (int it = 0; it < 8; it++) {
            int idx = t + it * 256;
            int p = idx >> 5, c4 = (idx & 31) * 4;
            const float* r0 = tile + (2 * p)     * LDT + c4;
            const float* r1 = tile + (2 * p + 1) * LDT + c4;
            uint4 o;
            o.x = packh(r0[0], r1[0]);
            o.y = packh(r0[1], r1[1]);
            o.z = packh(r0[2], r1[2]);
            o.w = packh(r0[3], r1[3]);
            *(uint4*)(g_h + ((size_t)b * (C_MID / 2) + (m0 >> 1) + p) * HW + p0 + c4) = o;
        }
    } else {
#pragma unroll
        for (int mi = 0; mi < 4; mi++) {
#pragma unroll
            for (int half = 0; half < 2; half++) {
                int r = m0 + (mtb + mi) * 16 + gr + half * 8;
                float bi = bias[r];
                const float* xrow = xres + ((size_t)b * C_IN + r) * HW + p0 + nw;
                float* orow = outp + ((size_t)b * C_IN + r) * HW + p0 + nw;
#pragma unroll
                for (int ni = 0; ni < 4; ni++) {
                    float2 xv = *(const float2*)(xrow + ni * 8 + tg * 2);
                    float2 o = make_float2(xv.x + acc[mi][ni][half * 2]     + bi,
                                           xv.y + acc[mi][ni][half * 2 + 1] + bi);
                    *(float2*)(orow + ni * 8 + tg * 2) = o;
                }
            }
        }
    }
}

// ---------------------------------------------------------------------------
extern "C" void kernel_launch(void* const* d_in, const int* in_sizes, int n_in,
                              void* d_out, int out_size) {
    const float* x    = (const float*)d_in[0];
    const float* emb  = (const float*)d_in[1];
    const float* gn_w = (const float*)d_in[2];
    const float* gn_b = (const float*)d_in[3];
    const float* w1   = (const float*)d_in[4];
    const float* b1   = (const float*)d_in[5];
    const float* we   = (const float*)d_in[6];
    const float* be   = (const float*)d_in[7];
    const float* w2   = (const float*)d_in[8];
    const float* b2   = (const float*)d_in[9];
    float* out = (float*)d_out;

    u32 *hbuf, *xnbuf;
    __half *w1f, *w2f;
    cudaGetSymbolAddress((void**)&hbuf, g_h);
    cudaGetSymbolAddress((void**)&xnbuf, g_xn);
    cudaGetSymbolAddress((void**)&w1f, g_w1f);
    cudaGetSymbolAddress((void**)&w2f, g_w2f);

    constexpr int SMEMB = 3 * (4096 + 32 * 136) * 4 + 1024;

    cudaFuncSetAttribute((const void*)mma_gemm<C_IN, C_MID, 1>,
                         cudaFuncAttributeMaxDynamicSharedMemorySize, SMEMB);
    cudaFuncSetAttribute((const void*)mma_gemm<C_MID, C_IN, 2>,
                         cudaFuncAttributeMaxDynamicSharedMemorySize, SMEMB);

    prep<<<GNBLK + 2 * W4BLK + EMBBLK, 256>>>(
        w1, w2, emb, we, be, x, gn_w, gn_b);

    mma_gemm<C_IN, C_MID, 1><<<dim3(C_MID / BM, HW / 128, BATCH), 256, SMEMB>>>(
        w1f, xnbuf, b1, nullptr, nullptr);
    mma_gemm<C_MID, C_IN, 2><<<dim3(C_IN / BM, HW / 128, BATCH), 256, SMEMB>>>(
        w2f, hbuf, b2, x, out);
}

// round 16
// speedup vs baseline: 1.1445x; 1.0304x over previous
#include <cuda_runtime.h>
#include <cuda_fp16.h>
#include <math.h>
#include <stdint.h>

#define C_IN   384
#define C_MID  1536
#define EMB_D  1024
#define BATCH  16
#define HW     1024
#define GROUPS 32
#define CPG    12
#define EPSV   1e-5f

#define BM 128
#define LDT 132

typedef unsigned int u32;

// ---------------- device scratch ----------------
__device__ u32 g_h[(size_t)BATCH * (C_MID / 2) * HW];   // h fp16 pair-major
__device__ u32 g_xn[(size_t)BATCH * (C_IN / 2) * HW];   // xn fp16 pair-major
__device__ float g_embout[BATCH * 2 * C_MID];
__device__ __half g_w1f[C_MID * C_IN];
__device__ __half g_w2f[C_IN * C_MID];
__device__ int g_cnt[BATCH * 8];                        // h-column completion counters

// ---------------- helpers ----------------
__device__ __forceinline__ u32 packh(float lo, float hi) {
    __half2 h = __floats2half2_rn(lo, hi);
    return *(u32*)&h;
}
__device__ __forceinline__ void mma16(float* c, const u32* a, const u32* b) {
    asm volatile(
        "mma.sync.aligned.m16n8k16.row.col.f32.f16.f16.f32 "
        "{%0,%1,%2,%3}, {%4,%5,%6,%7}, {%8,%9}, {%0,%1,%2,%3};\n"
        : "+f"(c[0]), "+f"(c[1]), "+f"(c[2]), "+f"(c[3])
        : "r"(a[0]), "r"(a[1]), "r"(a[2]), "r"(a[3]), "r"(b[0]), "r"(b[1]));
}
__device__ __forceinline__ void cp16(const void* s, const void* g) {
    uint32_t sa = (uint32_t)__cvta_generic_to_shared(s);
    asm volatile("cp.async.cg.shared.global [%0], [%1], 16;\n" :: "r"(sa), "l"(g));
}
#define CPCOMMIT() asm volatile("cp.async.commit_group;\n" ::: "memory")
#define CPWAIT(n)  asm volatile("cp.async.wait_group %0;\n" :: "n"(n) : "memory")

// ---------------------------------------------------------------------------
// Vectorized weight -> fragment order (one thread: 4 consecutive k of one m).
// ---------------------------------------------------------------------------
__device__ __forceinline__ void wtrans4(const float* __restrict__ w,
                                        __half* __restrict__ wf,
                                        int i4, int K) {
    int m = (i4 * 4) / K, k0 = (i4 * 4) % K;
    float4 v = *(const float4*)(w + (size_t)m * K + k0);
    int S = K >> 5;
    int mb = m >> 7, s = k0 >> 5;
    int kk = (k0 >> 4) & 1;
    int mt = (m >> 4) & 7;
    int r = m & 15, c0 = k0 & 15;
    int q = (r >> 3) | ((c0 >> 3) << 1);
    int lane0 = (r & 7) * 4 + ((c0 & 7) >> 1);
    u32* wfu = (u32*)wf;
    size_t base = ((((size_t)(mb * S + s) * 2 + kk) * 8 + mt) * 32) * 4 + q;
    wfu[base + (size_t)lane0 * 4]       = packh(v.x, v.y);
    wfu[base + (size_t)(lane0 + 1) * 4] = packh(v.z, v.w);
}

#define W4BLK ((C_MID * C_IN / 4) / 256)   // 576 blocks per weight
#define EMBBLK ((2 * C_MID) / 8)           // 384
#define GNBLK (GROUPS * BATCH)             // 512

// ---------------------------------------------------------------------------
// Fused prep: GroupNorm+xn | w1 | w2 | emb GEMM | counter reset.
// ---------------------------------------------------------------------------
__global__ void __launch_bounds__(256) prep(const float* __restrict__ w1,
                                            const float* __restrict__ w2,
                                            const float* __restrict__ emb,
                                            const float* __restrict__ we,
                                            const float* __restrict__ be,
                                            const float* __restrict__ x,
                                            const float* __restrict__ gn_w,
                                            const float* __restrict__ gn_b) {
    int bx = blockIdx.x;
    int t = threadIdx.x;

    if (bx < GNBLK) {
        int g = bx & (GROUPS - 1), b = bx >> 5;
        const float4* xp4 = (const float4*)(x + ((size_t)b * C_IN + (size_t)g * CPG) * HW);
        float4 xv[CPG];
#pragma unroll
        for (int it = 0; it < CPG; it++)
            xv[it] = __ldg(&xp4[t + it * 256]);

        float s = 0.f, ss = 0.f;
#pragma unroll
        for (int it = 0; it < CPG; it++) {
            float4 v = xv[it];
            s  += v.x + v.y + v.z + v.w;
            ss += v.x * v.x + v.y * v.y + v.z * v.z + v.w * v.w;
        }
#pragma unroll
        for (int off = 16; off; off >>= 1) {
            s  += __shfl_xor_sync(0xffffffffu, s, off);
            ss += __shfl_xor_sync(0xffffffffu, ss, off);
        }
        __shared__ float rs[8], rss[8];
        if ((t & 31) == 0) { rs[t >> 5] = s; rss[t >> 5] = ss; }
        __syncthreads();
        __shared__ float smu, srst;
        if (t == 0) {
            const int N = CPG * HW;
            float S = 0.f, SS = 0.f;
#pragma unroll
            for (int i = 0; i < 8; i++) { S += rs[i]; SS += rss[i]; }
            float mu  = S / (float)N;
            float var = SS / (float)N - mu * mu;
            smu = mu; srst = rsqrtf(var + EPSV);
        }
        __syncthreads();
        const float mu = smu, rst = srst;

        const int n4 = t * 4;
#pragma unroll
        for (int j = 0; j < CPG / 2; j++) {
            int c0 = g * CPG + j * 2;
            float a0 = rst * gn_w[c0],     b0 = gn_b[c0]     - mu * a0;
            float a1 = rst * gn_w[c0 + 1], b1 = gn_b[c0 + 1] - mu * a1;
            float4 x0 = xv[2 * j];
            float4 x1 = xv[2 * j + 1];
            uint4 o;
            o.x = packh(x0.x * a0 + b0, x1.x * a1 + b1);
            o.y = packh(x0.y * a0 + b0, x1.y * a1 + b1);
            o.z = packh(x0.z * a0 + b0, x1.z * a1 + b1);
            o.w = packh(x0.w * a0 + b0, x1.w * a1 + b1);
            *(uint4*)(g_xn + ((size_t)b * (C_IN / 2) + (c0 >> 1)) * HW + n4) = o;
        }
        return;
    }
    bx -= GNBLK;
    if (bx < W4BLK) {
        if (bx == 0 && t < BATCH * 8) g_cnt[t] = 0;   // reset dependency counters
        wtrans4(w1, g_w1f, bx * 256 + t, C_IN);
        return;
    }
    if (bx < 2 * W4BLK) {
        wtrans4(w2, g_w2f, (bx - W4BLK) * 256 + t, C_MID);
        return;
    }
    // ---- emb GEMM ----
    int w = t >> 5, lane = t & 31;
    int j = (bx - 2 * W4BLK) * 8 + w;
    const float4* wrow = (const float4*)(we + (size_t)j * EMB_D);
    float4 wv[8];
#pragma unroll
    for (int i = 0; i < 8; i++) wv[i] = wrow[lane + 32 * i];
#pragma unroll
    for (int b = 0; b < BATCH; b++) {
        const float4* er = (const float4*)(emb + (size_t)b * EMB_D);
        float acc = 0.f;
#pragma unroll
        for (int i = 0; i < 8; i++) {
            float4 ev = __ldg(&er[lane + 32 * i]);
            acc += wv[i].x * ev.x + wv[i].y * ev.y + wv[i].z * ev.z + wv[i].w * ev.w;
        }
#pragma unroll
        for (int off = 16; off; off >>= 1) acc += __shfl_xor_sync(0xffffffffu, acc, off);
        if (lane == 0) g_embout[b * (2 * C_MID) + j] = acc + be[j];
    }
}

// ---------------------------------------------------------------------------
// GEMM body (device fn). BK=64, NST=3, 128x128 tile, 8 warps 2m x 4n.
// EPI==1: silu+FiLM -> g_h; signals g_cnt. EPI==2: waits g_cnt; +x+b2 -> out.
// ---------------------------------------------------------------------------
template <int KTOT, int EPI>
__device__ __forceinline__ void gemm_body(
    int mb, int py, int b,
    const __half* __restrict__ Wf,
    const u32* __restrict__ Bsrc,
    const float* __restrict__ bias,
    const float* __restrict__ xres,
    float* __restrict__ outp,
    u32* sm, int t)
{
    constexpr int BK   = 64;
    constexpr int NST  = 3;
    constexpr int KK   = BK / 16;
    constexpr int LDB  = 136;
    constexpr int A_U  = BM * BK / 2;
    constexpr int STG  = A_U + (BK / 2) * LDB;
    constexpr int S    = KTOT / BK;

    const int m0 = mb * BM;
    const int p0 = py * 128;
    const int wid = t >> 5, lane = t & 31;
    const int gr = lane >> 2, tg = lane & 3;
    const int mtb = (wid >> 2) * 4;
    const int nw = (wid & 3) * 32;

    if (EPI == 2) {   // wait for the 12 producer tiles of this (b, py) column
        if (t == 0) {
            while (atomicAdd(&g_cnt[b * 8 + py], 0) != 12) __nanosleep(64);
            __threadfence();
        }
        __syncthreads();
    }

    const u32* Wb = (const u32*)Wf + (size_t)mb * (KTOT / 32) * 2048;
    const u32* Bb = Bsrc + (size_t)b * (KTOT / 2) * HW + p0;

    float acc[4][4][4];
#pragma unroll
    for (int i = 0; i < 4; i++)
#pragma unroll
        for (int j = 0; j < 4; j++)
#pragma unroll
            for (int q = 0; q < 4; q++) acc[i][j][q] = 0.f;

    auto fill = [&](int st) {
        u32* sA = sm + (st % NST) * STG;
        u32* sB = sA + A_U;
        const u32* gA = Wb + (size_t)st * A_U;
#pragma unroll
        for (int it = 0; it < A_U / 1024; it++)
            cp16(sA + it * 1024 + t * 4, gA + it * 1024 + t * 4);
#pragma unroll
        for (int it = 0; it < BK / 16; it++) {
            int idx = t + it * 256;
            int row = idx >> 5, c4 = (idx & 31) * 4;
            cp16(sB + row * LDB + c4, Bb + (size_t)(st * (BK / 2) + row) * HW + c4);
        }
        CPCOMMIT();
    };

#pragma unroll
    for (int p = 0; p < NST - 1; p++) fill(p);

    for (int s = 0; s < S; s++) {
        if (S - 1 - s >= 1) { CPWAIT(1); } else { CPWAIT(0); }
        __syncthreads();
        if (s + NST - 1 < S) fill(s + NST - 1);

        const u32* sA = sm + (s % NST) * STG;
        const u32* sB = sA + A_U;

#pragma unroll
        for (int kk = 0; kk < KK; kk++) {
            u32 af[4][4];
#pragma unroll
            for (int mi = 0; mi < 4; mi++) {
                const uint4 v = *(const uint4*)(sA + ((kk * 8 + mtb + mi) * 32 + lane) * 4);
                af[mi][0] = v.x; af[mi][1] = v.y; af[mi][2] = v.z; af[mi][3] = v.w;
            }
            u32 bf[4][2];
#pragma unroll
            for (int ni = 0; ni < 4; ni++) {
                int nc = nw + ni * 8 + gr;
                bf[ni][0] = sB[(kk * 8 + tg)     * LDB + nc];
                bf[ni][1] = sB[(kk * 8 + tg + 4) * LDB + nc];
            }
#pragma unroll
            for (int mi = 0; mi < 4; mi++)
#pragma unroll
                for (int ni = 0; ni < 4; ni++)
                    mma16(acc[mi][ni], af[mi], bf[ni]);
        }
    }
    __syncthreads();

    if (EPI == 1) {
        float* tile = (float*)sm;
        const float* sc = g_embout + b * 2 * C_MID;
#pragma unroll
        for (int mi = 0; mi < 4; mi++) {
#pragma unroll
            for (int half = 0; half < 2; half++) {
                int rl = (mtb + mi) * 16 + gr + half * 8;
                int r = m0 + rl;
                float bi    = bias[r];
                float scale = 1.f + sc[r];
                float shift = sc[C_MID + r];
#pragma unroll
                for (int ni = 0; ni < 4; ni++) {
                    float v0 = acc[mi][ni][half * 2]     + bi;
                    float v1 = acc[mi][ni][half * 2 + 1] + bi;
                    v0 = v0 / (1.f + __expf(-v0));
                    v1 = v1 / (1.f + __expf(-v1));
                    float2 o = make_float2(v0 * scale + shift, v1 * scale + shift);
                    *(float2*)(tile + rl * LDT + nw + ni * 8 + tg * 2) = o;
                }
            }
        }
        __syncthreads();
#pragma unroll
        for (int it = 0; it < 8; it++) {
            int idx = t + it * 256;
            int p = idx >> 5, c4 = (idx & 31) * 4;
            const float* r0 = tile + (2 * p)     * LDT + c4;
            const float* r1 = tile + (2 * p + 1) * LDT + c4;
            uint4 o;
            o.x = packh(r0[0], r1[0]);
            o.y = packh(r0[1], r1[1]);
            o.z = packh(r0[2], r1[2]);
            o.w = packh(r0[3], r1[3]);
            *(uint4*)(g_h + ((size_t)b * (C_MID / 2) + (m0 >> 1) + p) * HW + p0 + c4) = o;
        }
        // release: all stores visible before counter bump
        __threadfence();
        __syncthreads();
        if (t == 0) atomicAdd(&g_cnt[b * 8 + py], 1);
    } else {
#pragma unroll
        for (int mi = 0; mi < 4; mi++) {
#pragma unroll
            for (int half = 0; half < 2; half++) {
                int r = m0 + (mtb + mi) * 16 + gr + half * 8;
                float bi = bias[r];
                const float* xrow = xres + ((size_t)b * C_IN + r) * HW + p0 + nw;
                float* orow = outp + ((size_t)b * C_IN + r) * HW + p0 + nw;
#pragma unroll
                for (int ni = 0; ni < 4; ni++) {
                    float2 xv = *(const float2*)(xrow + ni * 8 + tg * 2);
                    float2 o = make_float2(xv.x + acc[mi][ni][half * 2]     + bi,
                                           xv.y + acc[mi][ni][half * 2 + 1] + bi);
                    *(float2*)(orow + ni * 8 + tg * 2) = o;
                }
            }
        }
    }
}

#define G1BLK (12 * 8 * BATCH)   // 1536 gemm1 tiles

// ---------------------------------------------------------------------------
// Combined GEMM launch: bids [0, G1BLK) = gemm1 (mb fast), rest = gemm2.
// ---------------------------------------------------------------------------
__global__ void __launch_bounds__(256, 2) gemms(
    const __half* __restrict__ w1f, const u32* __restrict__ xnb,
    const float* __restrict__ b1,
    const __half* __restrict__ w2f, const u32* __restrict__ hb,
    const float* __restrict__ b2,
    const float* __restrict__ x, float* __restrict__ outp)
{
    extern __shared__ float dsm[];
    u32* sm = (u32*)(((uintptr_t)dsm + 1023) & ~(uintptr_t)1023);
    int t = threadIdx.x;
    int bid = blockIdx.x;
    if (bid < G1BLK) {
        int mb = bid % 12, py = (bid / 12) & 7, b = bid / 96;
        gemm_body<C_IN, 1>(mb, py, b, w1f, xnb, b1, nullptr, nullptr, sm, t);
    } else {
        int r = bid - G1BLK;
        int mb = r % 3, py = (r / 3) & 7, b = r / 24;
        gemm_body<C_MID, 2>(mb, py, b, w2f, hb, b2, x, outp, sm, t);
    }
}

// ---------------------------------------------------------------------------
extern "C" void kernel_launch(void* const* d_in, const int* in_sizes, int n_in,
                              void* d_out, int out_size) {
    const float* x    = (const float*)d_in[0];
    const float* emb  = (const float*)d_in[1];
    const float* gn_w = (const float*)d_in[2];
    const float* gn_b = (const float*)d_in[3];
    const float* w1   = (const float*)d_in[4];
    const float* b1   = (const float*)d_in[5];
    const float* we   = (const float*)d_in[6];
    const float* be   = (const float*)d_in[7];
    const float* w2   = (const float*)d_in[8];
    const float* b2   = (const float*)d_in[9];
    float* out = (float*)d_out;

    u32 *hbuf, *xnbuf;
    __half *w1f, *w2f;
    cudaGetSymbolAddress((void**)&hbuf, g_h);
    cudaGetSymbolAddress((void**)&xnbuf, g_xn);
    cudaGetSymbolAddress((void**)&w1f, g_w1f);
    cudaGetSymbolAddress((void**)&w2f, g_w2f);

    constexpr int SMEMB = 3 * (4096 + 32 * 136) * 4 + 1024;

    cudaFuncSetAttribute((const void*)gemms,
                         cudaFuncAttributeMaxDynamicSharedMemorySize, SMEMB);

    prep<<<GNBLK + 2 * W4BLK + EMBBLK, 256>>>(
        w1, w2, emb, we, be, x, gn_w, gn_b);

    gemms<<<G1BLK + 3 * 8 * BATCH, 256, SMEMB>>>(
        w1f, xnbuf, b1, w2f, hbuf, b2, x, out);
}